// round 12
// baseline (speedup 1.0000x reference)
#include <cuda_runtime.h>
#include <cstdint>

#define D 128
#define NMAX 100000
#define EMAX 600000
#define CAP 64
#define PITCH  260   // weights pitch: %32==4 -> conflict-free fragment rows
#define IPITCH 68    // ins chunk pitch: %32==4, 16B-aligned rows

// Scratch
__device__ __align__(16) float g_h[(size_t)NMAX * D];
__device__ __align__(16) float g_agg[(size_t)NMAX * D];   // mean_agg (tf32 vals)
__device__ int  g_cnt_i[NMAX];
__device__ int  g_bucket[(size_t)NMAX * CAP];
__device__ int2 g_ovf_edges[EMAX];
__device__ int  g_ovf_cnt;

__device__ __forceinline__ float f2tf32f(float f) {
    uint32_t t;
    asm("cvt.rna.tf32.f32 %0, %1;" : "=r"(t) : "f"(f));
    return __uint_as_float(t);
}
__device__ __forceinline__ uint32_t smem_u32(const void* p) {
    uint32_t a;
    asm("{ .reg .u64 t; cvta.to.shared.u64 t, %1; cvt.u32.u64 %0, t; }" : "=r"(a) : "l"(p));
    return a;
}
__device__ __forceinline__ void cp16(uint32_t dst, const void* src, bool pred) {
    int sz = pred ? 16 : 0;   // src-size 0 -> zero-fill
    asm volatile("cp.async.cg.shared.global [%0], [%1], 16, %2;"
                 :: "r"(dst), "l"(src), "r"(sz) : "memory");
}

// ---------------------------------------------------------------------------
// Kernel 1: merged LN (+ReLU+dropout, tf32-rounded h) and bucket fill.
// Blocks [0, lnB) do LN rows; blocks [lnB, lnB+fillB) do edges.
// Counters: g_cnt_i zeroed by aggregate (prev replay), g_ovf_cnt by gemm.
// ---------------------------------------------------------------------------
__global__ void ln_fill_kernel(const float* __restrict__ x,
                               const float* __restrict__ mask,
                               const float* __restrict__ gamma,
                               const float* __restrict__ beta,
                               const int* __restrict__ ei,
                               int N, int E, int lnB) {
    if ((int)blockIdx.x < lnB) {
        int warp = threadIdx.x >> 5;
        int lane = threadIdx.x & 31;
        int row  = blockIdx.x * 8 + warp;
        if (row >= N) return;

        const float4 xv = reinterpret_cast<const float4*>(x)[row * 32 + lane];
        float s  = xv.x + xv.y + xv.z + xv.w;
        float ss = xv.x * xv.x + xv.y * xv.y + xv.z * xv.z + xv.w * xv.w;
#pragma unroll
        for (int o = 16; o > 0; o >>= 1) {
            s  += __shfl_xor_sync(0xFFFFFFFFu, s,  o);
            ss += __shfl_xor_sync(0xFFFFFFFFu, ss, o);
        }
        const float mu   = s * (1.0f / 128.0f);
        const float var  = ss * (1.0f / 128.0f) - mu * mu;
        const float rstd = rsqrtf(var + 1e-5f);

        const float4 g = reinterpret_cast<const float4*>(gamma)[lane];
        const float4 b = reinterpret_cast<const float4*>(beta)[lane];
        const float4 m = reinterpret_cast<const float4*>(mask)[row * 32 + lane];

        float4 hv;
        hv.x = f2tf32f(fmaxf((xv.x - mu) * rstd * g.x + b.x, 0.0f) * m.x);
        hv.y = f2tf32f(fmaxf((xv.y - mu) * rstd * g.y + b.y, 0.0f) * m.y);
        hv.z = f2tf32f(fmaxf((xv.z - mu) * rstd * g.z + b.z, 0.0f) * m.z);
        hv.w = f2tf32f(fmaxf((xv.w - mu) * rstd * g.w + b.w, 0.0f) * m.w);

        reinterpret_cast<float4*>(g_h)[row * 32 + lane] = hv;
    } else {
        int e = (blockIdx.x - lnB) * blockDim.x + threadIdx.x;
        if (e >= E) return;
        const int s = __ldg(&ei[e]);
        const int d = __ldg(&ei[E + e]);
        int pos = atomicAdd(&g_cnt_i[d], 1);
        if (pos < CAP) g_bucket[(size_t)d * CAP + pos] = s;
        else {
            int idx = atomicAdd(&g_ovf_cnt, 1);
            g_ovf_edges[idx] = make_int2(s, d);
        }
    }
}

// ---------------------------------------------------------------------------
// Kernel 2: gather-aggregate; writes tf32-rounded mean; re-zeroes counters.
// ---------------------------------------------------------------------------
__global__ void aggregate_kernel(int N) {
    int warp = threadIdx.x >> 5;
    int lane = threadIdx.x & 31;
    int d    = blockIdx.x * 8 + warp;
    if (d >= N) return;

    const int n  = g_cnt_i[d];
    __syncwarp();                       // all lanes read n before lane0 clears
    if (lane == 0) g_cnt_i[d] = 0;      // reset for next graph replay

    const int nb = n < CAP ? n : CAP;
    const int* bk = &g_bucket[(size_t)d * CAP];

    float4 acc = make_float4(0.f, 0.f, 0.f, 0.f);
    int j = 0;
    for (; j + 2 <= nb; j += 2) {
        int s0 = __ldg(&bk[j]);
        int s1 = __ldg(&bk[j + 1]);
        float4 v0 = reinterpret_cast<const float4*>(g_h)[(size_t)s0 * 32 + lane];
        float4 v1 = reinterpret_cast<const float4*>(g_h)[(size_t)s1 * 32 + lane];
        acc.x += v0.x + v1.x; acc.y += v0.y + v1.y;
        acc.z += v0.z + v1.z; acc.w += v0.w + v1.w;
    }
    if (j < nb) {
        int s0 = __ldg(&bk[j]);
        float4 v0 = reinterpret_cast<const float4*>(g_h)[(size_t)s0 * 32 + lane];
        acc.x += v0.x; acc.y += v0.y; acc.z += v0.z; acc.w += v0.w;
    }
    const int novf = g_ovf_cnt;
    for (int t = 0; t < novf; ++t) {
        int2 p = g_ovf_edges[t];
        if (p.y == d) {
            float4 v = reinterpret_cast<const float4*>(g_h)[(size_t)p.x * 32 + lane];
            acc.x += v.x; acc.y += v.y; acc.z += v.z; acc.w += v.w;
        }
    }
    const float inv = 1.0f / fmaxf((float)n, 1.0f);
    float4 o;
    o.x = f2tf32f(acc.x * inv);
    o.y = f2tf32f(acc.y * inv);
    o.z = f2tf32f(acc.z * inv);
    o.w = f2tf32f(acc.w * inv);
    reinterpret_cast<float4*>(g_agg)[(size_t)d * 32 + lane] = o;
}

// ---------------------------------------------------------------------------
// Kernel 3: tf32 mma.sync GEMM, cp.async double-buffered K chunks.
// Exact R10 body (72.7us measured): scalar fragment loads keep regs at 62,
// under the 64-reg ceiling imposed by 1024 threads (paired-reg LDS.64
// variants spill and run 2x slower).
//   out = [mean_agg | h] (Nx256) @ Wcat^T + b_l
// Block M=128, N=128; K in 4 chunks of 64. 32 warps (4rg x 8cg), warp 2m x 2n.
// ---------------------------------------------------------------------------
__global__ void __launch_bounds__(1024, 1)
gemm_mma_kernel(const float* __restrict__ Wl, const float* __restrict__ bl,
                const float* __restrict__ Wr, float* __restrict__ out, int N) {
    extern __shared__ float sm[];
    float* Wt   = sm;                          // [128][PITCH]
    float* bufs = sm + 128 * PITCH;            // 2 x [128][IPITCH]
    const uint32_t bufs_u32 = smem_u32(bufs);

    if (blockIdx.x == 0 && threadIdx.x == 0) g_ovf_cnt = 0;  // reset for next replay

    const int tid  = threadIdx.x;
    const int lane = tid & 31;
    const int wid  = tid >> 5;
    const int g    = lane >> 2;
    const int t    = lane & 3;
    const int mg   = wid >> 3;        // 0..3: rows mg*32
    const int ng   = wid & 7;         // 0..7: cols ng*16
    const int r0   = mg * 32;
    const int c0   = ng * 16;

    // Stage weights (tf32-rounded): Wt[n][k]
    for (int idx = tid; idx < 128 * 256; idx += 1024) {
        int n = idx >> 8;
        int k = idx & 255;
        float w = (k < 128) ? Wl[n * 128 + k] : Wr[n * 128 + (k - 128)];
        Wt[n * PITCH + k] = f2tf32f(w);
    }

    float2 bias[2];
#pragma unroll
    for (int n = 0; n < 2; ++n) {
        int col = c0 + n * 8 + 2 * t;
        bias[n].x = __ldg(&bl[col]);
        bias[n].y = __ldg(&bl[col + 1]);
    }

    const int sr  = tid >> 4;          // staging row 0..63 (u adds +64)
    const int sfo = tid & 15;          // staging float4 col 0..15
    const int ntiles = (N + 127) / 128;

    for (int tile = blockIdx.x; tile < ntiles; tile += gridDim.x) {
        const int rowbase = tile * 128;

        // prefetch chunk 0 (cols 0..63 = g_agg cols 0..63)
#pragma unroll
        for (int u = 0; u < 2; ++u) {
            int r = sr + u * 64;
            int grow = rowbase + r;
            const float* src = g_agg + (size_t)grow * 128 + sfo * 4;
            uint32_t dst = bufs_u32 + (uint32_t)(r * IPITCH + sfo * 4) * 4u;
            cp16(dst, src, grow < N);
        }
        asm volatile("cp.async.commit_group;" ::: "memory");

        float acc[2][2][4];
#pragma unroll
        for (int m = 0; m < 2; ++m)
#pragma unroll
            for (int n = 0; n < 2; ++n)
#pragma unroll
                for (int i = 0; i < 4; ++i) acc[m][n][i] = 0.0f;

#pragma unroll
        for (int c = 0; c < 4; ++c) {
            if (c < 3) {
                const int cc = c + 1;
#pragma unroll
                for (int u = 0; u < 2; ++u) {
                    int r = sr + u * 64;
                    int grow = rowbase + r;
                    int colb = cc * 64 + sfo * 4;   // 64..255
                    const float* src = (colb < 128)
                        ? g_agg + (size_t)grow * 128 + colb
                        : g_h   + (size_t)grow * 128 + (colb - 128);
                    uint32_t dst = bufs_u32
                        + (uint32_t)(((cc & 1) * 128 + r) * IPITCH + sfo * 4) * 4u;
                    cp16(dst, src, grow < N);
                }
                asm volatile("cp.async.commit_group;" ::: "memory");
                asm volatile("cp.async.wait_group 1;" ::: "memory");
            } else {
                asm volatile("cp.async.wait_group 0;" ::: "memory");
            }
            __syncthreads();

            const float* Abase = bufs + (c & 1) * 128 * IPITCH + (r0 + g) * IPITCH + t;
            const float* Bbase = Wt + (c0 + g) * PITCH + c * 64 + t;

#pragma unroll
            for (int ks = 0; ks < 8; ++ks) {
                const float* ap = Abase + ks * 8;
                const float* bp = Bbase + ks * 8;

                uint32_t a[2][4];
#pragma unroll
                for (int m = 0; m < 2; ++m) {
                    const float* p = ap + m * 16 * IPITCH;
                    a[m][0] = __float_as_uint(p[0]);
                    a[m][1] = __float_as_uint(p[8 * IPITCH]);
                    a[m][2] = __float_as_uint(p[4]);
                    a[m][3] = __float_as_uint(p[8 * IPITCH + 4]);
                }
                uint32_t b[2][2];
#pragma unroll
                for (int n = 0; n < 2; ++n) {
                    const float* p = bp + n * 8 * PITCH;
                    b[n][0] = __float_as_uint(p[0]);
                    b[n][1] = __float_as_uint(p[4]);
                }
#pragma unroll
                for (int m = 0; m < 2; ++m)
#pragma unroll
                    for (int n = 0; n < 2; ++n) {
                        asm("mma.sync.aligned.m16n8k8.row.col.f32.tf32.tf32.f32 "
                            "{%0,%1,%2,%3}, {%4,%5,%6,%7}, {%8,%9}, {%0,%1,%2,%3};"
                            : "+f"(acc[m][n][0]), "+f"(acc[m][n][1]),
                              "+f"(acc[m][n][2]), "+f"(acc[m][n][3])
                            : "r"(a[m][0]), "r"(a[m][1]), "r"(a[m][2]), "r"(a[m][3]),
                              "r"(b[n][0]), "r"(b[n][1]));
                    }
            }
            __syncthreads();
        }

        // Epilogue: rows {r0 + m*16 + g, +8}, cols c0 + n*8 + 2t (+1)
#pragma unroll
        for (int m = 0; m < 2; ++m) {
            int row0 = rowbase + r0 + m * 16 + g;
            int row1 = row0 + 8;
#pragma unroll
            for (int n = 0; n < 2; ++n) {
                int colh = (c0 + n * 8 + 2 * t) >> 1;
                if (row0 < N) {
                    float2 o0 = make_float2(acc[m][n][0] + bias[n].x,
                                            acc[m][n][1] + bias[n].y);
                    reinterpret_cast<float2*>(out)[(size_t)row0 * 64 + colh] = o0;
                }
                if (row1 < N) {
                    float2 o1 = make_float2(acc[m][n][2] + bias[n].x,
                                            acc[m][n][3] + bias[n].y);
                    reinterpret_cast<float2*>(out)[(size_t)row1 * 64 + colh] = o1;
                }
            }
        }
    }
}

// ---------------------------------------------------------------------------
extern "C" void kernel_launch(void* const* d_in, const int* in_sizes, int n_in,
                              void* d_out, int out_size) {
    const float* x     = (const float*)d_in[0];
    const int*   eidx  = (const int*)d_in[1];   // int32 (JAX x64 disabled)
    const float* mask  = (const float*)d_in[2];
    const float* gamma = (const float*)d_in[3];
    const float* beta  = (const float*)d_in[4];
    const float* Wl    = (const float*)d_in[5];
    const float* bl    = (const float*)d_in[6];
    const float* Wr    = (const float*)d_in[7];
    float*       out   = (float*)d_out;

    const int N = in_sizes[0] / D;
    const int E = in_sizes[1] / 2;

    const int lnB   = (N + 7) / 8;
    const int fillB = (E + 255) / 256;
    ln_fill_kernel<<<lnB + fillB, 256>>>(x, mask, gamma, beta, eidx, N, E, lnB);
    aggregate_kernel<<<(N + 7) / 8, 256>>>(N);

    {
        int smem = (128 * PITCH + 2 * 128 * IPITCH) * (int)sizeof(float);  // 202,752 B
        cudaFuncSetAttribute(gemm_mma_kernel, cudaFuncAttributeMaxDynamicSharedMemorySize, smem);
        int nsm = 148;
        cudaDeviceGetAttribute(&nsm, cudaDevAttrMultiProcessorCount, 0);
        gemm_mma_kernel<<<nsm, 1024, smem>>>(Wl, bl, Wr, out, N);
    }
}

// round 13
// speedup vs baseline: 1.6629x; 1.6629x over previous
#include <cuda_runtime.h>
#include <cstdint>

#define D 128
#define NMAX 100000
#define EMAX 600000
#define CAP 64
#define PITCH  260   // weights pitch: %32==4 -> conflict-free fragment rows
#define IPITCH 68    // ins chunk pitch: %32==4, 16B-aligned rows

// Scratch
__device__ __align__(16) float g_h[(size_t)NMAX * D];
__device__ __align__(16) float g_agg[(size_t)NMAX * D];   // mean_agg (tf32 vals)
__device__ int  g_cnt_i[NMAX];
__device__ int  g_bucket[(size_t)NMAX * CAP];
__device__ int2 g_ovf_edges[EMAX];
__device__ int  g_ovf_cnt;

__device__ __forceinline__ float f2tf32f(float f) {
    uint32_t t;
    asm("cvt.rna.tf32.f32 %0, %1;" : "=r"(t) : "f"(f));
    return __uint_as_float(t);
}
__device__ __forceinline__ uint32_t smem_u32(const void* p) {
    uint32_t a;
    asm("{ .reg .u64 t; cvta.to.shared.u64 t, %1; cvt.u32.u64 %0, t; }" : "=r"(a) : "l"(p));
    return a;
}
__device__ __forceinline__ void cp16(uint32_t dst, const void* src, bool pred) {
    int sz = pred ? 16 : 0;   // src-size 0 -> zero-fill
    asm volatile("cp.async.cg.shared.global [%0], [%1], 16, %2;"
                 :: "r"(dst), "l"(src), "r"(sz) : "memory");
}

// ---------------------------------------------------------------------------
// Kernel 1: LayerNorm -> ReLU -> dropout; h pre-rounded to tf32 (RNA).
// Zeroes g_cnt_i and g_ovf_cnt for the fill that follows (R10 lifecycle).
// ---------------------------------------------------------------------------
__global__ void ln_relu_drop_kernel(const float* __restrict__ x,
                                    const float* __restrict__ mask,
                                    const float* __restrict__ gamma,
                                    const float* __restrict__ beta,
                                    int N) {
    int warp = threadIdx.x >> 5;
    int lane = threadIdx.x & 31;
    int row  = blockIdx.x * 8 + warp;
    if (blockIdx.x == 0 && threadIdx.x == 0) g_ovf_cnt = 0;
    if (row >= N) return;

    const float4 xv = reinterpret_cast<const float4*>(x)[row * 32 + lane];
    float s  = xv.x + xv.y + xv.z + xv.w;
    float ss = xv.x * xv.x + xv.y * xv.y + xv.z * xv.z + xv.w * xv.w;
#pragma unroll
    for (int o = 16; o > 0; o >>= 1) {
        s  += __shfl_xor_sync(0xFFFFFFFFu, s,  o);
        ss += __shfl_xor_sync(0xFFFFFFFFu, ss, o);
    }
    const float mu   = s * (1.0f / 128.0f);
    const float var  = ss * (1.0f / 128.0f) - mu * mu;
    const float rstd = rsqrtf(var + 1e-5f);

    const float4 g = reinterpret_cast<const float4*>(gamma)[lane];
    const float4 b = reinterpret_cast<const float4*>(beta)[lane];
    const float4 m = reinterpret_cast<const float4*>(mask)[row * 32 + lane];

    float4 hv;
    hv.x = f2tf32f(fmaxf((xv.x - mu) * rstd * g.x + b.x, 0.0f) * m.x);
    hv.y = f2tf32f(fmaxf((xv.y - mu) * rstd * g.y + b.y, 0.0f) * m.y);
    hv.z = f2tf32f(fmaxf((xv.z - mu) * rstd * g.z + b.z, 0.0f) * m.z);
    hv.w = f2tf32f(fmaxf((xv.w - mu) * rstd * g.w + b.w, 0.0f) * m.w);

    reinterpret_cast<float4*>(g_h)[row * 32 + lane] = hv;
    if (lane == 0) g_cnt_i[row] = 0;
}

// ---------------------------------------------------------------------------
// Kernel 2a: bucket fill (int atomics only).
// ---------------------------------------------------------------------------
__global__ void fill_kernel(const int* __restrict__ ei, int E) {
    int e = blockIdx.x * blockDim.x + threadIdx.x;
    if (e >= E) return;
    const int s = __ldg(&ei[e]);
    const int d = __ldg(&ei[E + e]);
    int pos = atomicAdd(&g_cnt_i[d], 1);
    if (pos < CAP) g_bucket[(size_t)d * CAP + pos] = s;
    else {
        int idx = atomicAdd(&g_ovf_cnt, 1);
        g_ovf_edges[idx] = make_int2(s, d);
    }
}

// ---------------------------------------------------------------------------
// Kernel 2b: gather-aggregate; writes tf32-rounded mean.
// x4 unrolled gather for MLP=4 on the random 512B row loads.
// ---------------------------------------------------------------------------
__global__ void aggregate_kernel(int N) {
    int warp = threadIdx.x >> 5;
    int lane = threadIdx.x & 31;
    int d    = blockIdx.x * 8 + warp;
    if (d >= N) return;

    const int n  = g_cnt_i[d];
    const int nb = n < CAP ? n : CAP;
    const int* bk = &g_bucket[(size_t)d * CAP];

    float4 acc = make_float4(0.f, 0.f, 0.f, 0.f);
    int j = 0;
    for (; j + 4 <= nb; j += 4) {   // MLP=4
        int s0 = __ldg(&bk[j]);
        int s1 = __ldg(&bk[j + 1]);
        int s2 = __ldg(&bk[j + 2]);
        int s3 = __ldg(&bk[j + 3]);
        float4 v0 = reinterpret_cast<const float4*>(g_h)[(size_t)s0 * 32 + lane];
        float4 v1 = reinterpret_cast<const float4*>(g_h)[(size_t)s1 * 32 + lane];
        float4 v2 = reinterpret_cast<const float4*>(g_h)[(size_t)s2 * 32 + lane];
        float4 v3 = reinterpret_cast<const float4*>(g_h)[(size_t)s3 * 32 + lane];
        acc.x += (v0.x + v1.x) + (v2.x + v3.x);
        acc.y += (v0.y + v1.y) + (v2.y + v3.y);
        acc.z += (v0.z + v1.z) + (v2.z + v3.z);
        acc.w += (v0.w + v1.w) + (v2.w + v3.w);
    }
    for (; j < nb; ++j) {
        int s0 = __ldg(&bk[j]);
        float4 v0 = reinterpret_cast<const float4*>(g_h)[(size_t)s0 * 32 + lane];
        acc.x += v0.x; acc.y += v0.y; acc.z += v0.z; acc.w += v0.w;
    }
    const int novf = g_ovf_cnt;     // 0 in practice
    for (int t = 0; t < novf; ++t) {
        int2 p = g_ovf_edges[t];
        if (p.y == d) {
            float4 v = reinterpret_cast<const float4*>(g_h)[(size_t)p.x * 32 + lane];
            acc.x += v.x; acc.y += v.y; acc.z += v.z; acc.w += v.w;
        }
    }
    const float inv = 1.0f / fmaxf((float)n, 1.0f);
    float4 o;
    o.x = f2tf32f(acc.x * inv);
    o.y = f2tf32f(acc.y * inv);
    o.z = f2tf32f(acc.z * inv);
    o.w = f2tf32f(acc.w * inv);
    reinterpret_cast<float4*>(g_agg)[(size_t)d * 32 + lane] = o;
}

// ---------------------------------------------------------------------------
// Kernel 3: tf32 mma.sync GEMM, cp.async double-buffered K chunks.
// Byte-for-byte the 72.7us R10 body.
//   out = [mean_agg | h] (Nx256) @ Wcat^T + b_l
// Block M=128, N=128; K in 4 chunks of 64. 32 warps (4rg x 8cg), warp 2m x 2n.
// ---------------------------------------------------------------------------
__global__ void __launch_bounds__(1024, 1)
gemm_mma_kernel(const float* __restrict__ Wl, const float* __restrict__ bl,
                const float* __restrict__ Wr, float* __restrict__ out, int N) {
    extern __shared__ float sm[];
    float* Wt   = sm;                          // [128][PITCH]
    float* bufs = sm + 128 * PITCH;            // 2 x [128][IPITCH]
    const uint32_t bufs_u32 = smem_u32(bufs);

    const int tid  = threadIdx.x;
    const int lane = tid & 31;
    const int wid  = tid >> 5;
    const int g    = lane >> 2;
    const int t    = lane & 3;
    const int mg   = wid >> 3;        // 0..3: rows mg*32
    const int ng   = wid & 7;         // 0..7: cols ng*16
    const int r0   = mg * 32;
    const int c0   = ng * 16;

    // Stage weights (tf32-rounded): Wt[n][k]
    for (int idx = tid; idx < 128 * 256; idx += 1024) {
        int n = idx >> 8;
        int k = idx & 255;
        float w = (k < 128) ? Wl[n * 128 + k] : Wr[n * 128 + (k - 128)];
        Wt[n * PITCH + k] = f2tf32f(w);
    }

    float2 bias[2];
#pragma unroll
    for (int n = 0; n < 2; ++n) {
        int col = c0 + n * 8 + 2 * t;
        bias[n].x = __ldg(&bl[col]);
        bias[n].y = __ldg(&bl[col + 1]);
    }

    const int sr  = tid >> 4;          // staging row 0..63 (u adds +64)
    const int sfo = tid & 15;          // staging float4 col 0..15
    const int ntiles = (N + 127) / 128;

    for (int tile = blockIdx.x; tile < ntiles; tile += gridDim.x) {
        const int rowbase = tile * 128;

        // prefetch chunk 0 (cols 0..63 = g_agg cols 0..63)
#pragma unroll
        for (int u = 0; u < 2; ++u) {
            int r = sr + u * 64;
            int grow = rowbase + r;
            const float* src = g_agg + (size_t)grow * 128 + sfo * 4;
            uint32_t dst = bufs_u32 + (uint32_t)(r * IPITCH + sfo * 4) * 4u;
            cp16(dst, src, grow < N);
        }
        asm volatile("cp.async.commit_group;" ::: "memory");

        float acc[2][2][4];
#pragma unroll
        for (int m = 0; m < 2; ++m)
#pragma unroll
            for (int n = 0; n < 2; ++n)
#pragma unroll
                for (int i = 0; i < 4; ++i) acc[m][n][i] = 0.0f;

#pragma unroll
        for (int c = 0; c < 4; ++c) {
            if (c < 3) {
                const int cc = c + 1;
#pragma unroll
                for (int u = 0; u < 2; ++u) {
                    int r = sr + u * 64;
                    int grow = rowbase + r;
                    int colb = cc * 64 + sfo * 4;   // 64..255
                    const float* src = (colb < 128)
                        ? g_agg + (size_t)grow * 128 + colb
                        : g_h   + (size_t)grow * 128 + (colb - 128);
                    uint32_t dst = bufs_u32
                        + (uint32_t)(((cc & 1) * 128 + r) * IPITCH + sfo * 4) * 4u;
                    cp16(dst, src, grow < N);
                }
                asm volatile("cp.async.commit_group;" ::: "memory");
                asm volatile("cp.async.wait_group 1;" ::: "memory");
            } else {
                asm volatile("cp.async.wait_group 0;" ::: "memory");
            }
            __syncthreads();

            const float* Abase = bufs + (c & 1) * 128 * IPITCH + (r0 + g) * IPITCH + t;
            const float* Bbase = Wt + (c0 + g) * PITCH + c * 64 + t;

#pragma unroll
            for (int ks = 0; ks < 8; ++ks) {
                const float* ap = Abase + ks * 8;
                const float* bp = Bbase + ks * 8;

                uint32_t a[2][4];
#pragma unroll
                for (int m = 0; m < 2; ++m) {
                    const float* p = ap + m * 16 * IPITCH;
                    a[m][0] = __float_as_uint(p[0]);
                    a[m][1] = __float_as_uint(p[8 * IPITCH]);
                    a[m][2] = __float_as_uint(p[4]);
                    a[m][3] = __float_as_uint(p[8 * IPITCH + 4]);
                }
                uint32_t b[2][2];
#pragma unroll
                for (int n = 0; n < 2; ++n) {
                    const float* p = bp + n * 8 * PITCH;
                    b[n][0] = __float_as_uint(p[0]);
                    b[n][1] = __float_as_uint(p[4]);
                }
#pragma unroll
                for (int m = 0; m < 2; ++m)
#pragma unroll
                    for (int n = 0; n < 2; ++n) {
                        asm("mma.sync.aligned.m16n8k8.row.col.f32.tf32.tf32.f32 "
                            "{%0,%1,%2,%3}, {%4,%5,%6,%7}, {%8,%9}, {%0,%1,%2,%3};"
                            : "+f"(acc[m][n][0]), "+f"(acc[m][n][1]),
                              "+f"(acc[m][n][2]), "+f"(acc[m][n][3])
                            : "r"(a[m][0]), "r"(a[m][1]), "r"(a[m][2]), "r"(a[m][3]),
                              "r"(b[n][0]), "r"(b[n][1]));
                    }
            }
            __syncthreads();
        }

        // Epilogue: rows {r0 + m*16 + g, +8}, cols c0 + n*8 + 2t (+1)
#pragma unroll
        for (int m = 0; m < 2; ++m) {
            int row0 = rowbase + r0 + m * 16 + g;
            int row1 = row0 + 8;
#pragma unroll
            for (int n = 0; n < 2; ++n) {
                int colh = (c0 + n * 8 + 2 * t) >> 1;
                if (row0 < N) {
                    float2 o0 = make_float2(acc[m][n][0] + bias[n].x,
                                            acc[m][n][1] + bias[n].y);
                    reinterpret_cast<float2*>(out)[(size_t)row0 * 64 + colh] = o0;
                }
                if (row1 < N) {
                    float2 o1 = make_float2(acc[m][n][2] + bias[n].x,
                                            acc[m][n][3] + bias[n].y);
                    reinterpret_cast<float2*>(out)[(size_t)row1 * 64 + colh] = o1;
                }
            }
        }
    }
}

// ---------------------------------------------------------------------------
extern "C" void kernel_launch(void* const* d_in, const int* in_sizes, int n_in,
                              void* d_out, int out_size) {
    const float* x     = (const float*)d_in[0];
    const int*   eidx  = (const int*)d_in[1];   // int32 (JAX x64 disabled)
    const float* mask  = (const float*)d_in[2];
    const float* gamma = (const float*)d_in[3];
    const float* beta  = (const float*)d_in[4];
    const float* Wl    = (const float*)d_in[5];
    const float* bl    = (const float*)d_in[6];
    const float* Wr    = (const float*)d_in[7];
    float*       out   = (float*)d_out;

    const int N = in_sizes[0] / D;
    const int E = in_sizes[1] / 2;

    ln_relu_drop_kernel<<<(N + 7) / 8, 256>>>(x, mask, gamma, beta, N);
    fill_kernel<<<(E + 255) / 256, 256>>>(eidx, E);
    aggregate_kernel<<<(N + 7) / 8, 256>>>(N);

    {
        int smem = (128 * PITCH + 2 * 128 * IPITCH) * (int)sizeof(float);  // 202,752 B
        cudaFuncSetAttribute(gemm_mma_kernel, cudaFuncAttributeMaxDynamicSharedMemorySize, smem);
        int nsm = 148;
        cudaDeviceGetAttribute(&nsm, cudaDevAttrMultiProcessorCount, 0);
        gemm_mma_kernel<<<nsm, 1024, smem>>>(Wl, bl, Wr, out, N);
    }
}

// round 14
// speedup vs baseline: 1.7220x; 1.0356x over previous
#include <cuda_runtime.h>
#include <cstdint>

#define D 128
#define NMAX 100000
#define EMAX 600000
#define CAP 64
#define PITCH  260   // weights pitch: %32==4 -> conflict-free fragment rows
#define IPITCH 68    // ins chunk pitch: %32==4, 16B-aligned rows

// Scratch
__device__ __align__(16) float g_h[(size_t)NMAX * D];
__device__ __align__(16) float g_agg[(size_t)NMAX * D];   // mean_agg (tf32 vals)
__device__ int  g_cnt_i[NMAX];
__device__ int  g_bucket[(size_t)NMAX * CAP];
__device__ int2 g_ovf_edges[EMAX];
__device__ int  g_ovf_cnt;

__device__ __forceinline__ float f2tf32f(float f) {
    uint32_t t;
    asm("cvt.rna.tf32.f32 %0, %1;" : "=r"(t) : "f"(f));
    return __uint_as_float(t);
}
__device__ __forceinline__ uint32_t smem_u32(const void* p) {
    uint32_t a;
    asm("{ .reg .u64 t; cvta.to.shared.u64 t, %1; cvt.u32.u64 %0, t; }" : "=r"(a) : "l"(p));
    return a;
}
__device__ __forceinline__ void cp16(uint32_t dst, const void* src, bool pred) {
    int sz = pred ? 16 : 0;   // src-size 0 -> zero-fill
    asm volatile("cp.async.cg.shared.global [%0], [%1], 16, %2;"
                 :: "r"(dst), "l"(src), "r"(sz) : "memory");
}

// ---------------------------------------------------------------------------
// Kernel 1: LayerNorm -> ReLU -> dropout; h pre-rounded to tf32 (RNA).
// Zeroes g_cnt_i and g_ovf_cnt for the fill that follows.
// ---------------------------------------------------------------------------
__global__ void ln_relu_drop_kernel(const float* __restrict__ x,
                                    const float* __restrict__ mask,
                                    const float* __restrict__ gamma,
                                    const float* __restrict__ beta,
                                    int N) {
    int warp = threadIdx.x >> 5;
    int lane = threadIdx.x & 31;
    int row  = blockIdx.x * 8 + warp;
    if (blockIdx.x == 0 && threadIdx.x == 0) g_ovf_cnt = 0;
    if (row >= N) return;

    const float4 xv = reinterpret_cast<const float4*>(x)[row * 32 + lane];
    float s  = xv.x + xv.y + xv.z + xv.w;
    float ss = xv.x * xv.x + xv.y * xv.y + xv.z * xv.z + xv.w * xv.w;
#pragma unroll
    for (int o = 16; o > 0; o >>= 1) {
        s  += __shfl_xor_sync(0xFFFFFFFFu, s,  o);
        ss += __shfl_xor_sync(0xFFFFFFFFu, ss, o);
    }
    const float mu   = s * (1.0f / 128.0f);
    const float var  = ss * (1.0f / 128.0f) - mu * mu;
    const float rstd = rsqrtf(var + 1e-5f);

    const float4 g = reinterpret_cast<const float4*>(gamma)[lane];
    const float4 b = reinterpret_cast<const float4*>(beta)[lane];
    const float4 m = reinterpret_cast<const float4*>(mask)[row * 32 + lane];

    float4 hv;
    hv.x = f2tf32f(fmaxf((xv.x - mu) * rstd * g.x + b.x, 0.0f) * m.x);
    hv.y = f2tf32f(fmaxf((xv.y - mu) * rstd * g.y + b.y, 0.0f) * m.y);
    hv.z = f2tf32f(fmaxf((xv.z - mu) * rstd * g.z + b.z, 0.0f) * m.z);
    hv.w = f2tf32f(fmaxf((xv.w - mu) * rstd * g.w + b.w, 0.0f) * m.w);

    reinterpret_cast<float4*>(g_h)[row * 32 + lane] = hv;
    if (lane == 0) g_cnt_i[row] = 0;
}

// ---------------------------------------------------------------------------
// Kernel 2a: bucket fill (int atomics only).
// ---------------------------------------------------------------------------
__global__ void fill_kernel(const int* __restrict__ ei, int E) {
    int e = blockIdx.x * blockDim.x + threadIdx.x;
    if (e >= E) return;
    const int s = __ldg(&ei[e]);
    const int d = __ldg(&ei[E + e]);
    int pos = atomicAdd(&g_cnt_i[d], 1);
    if (pos < CAP) g_bucket[(size_t)d * CAP + pos] = s;
    else {
        int idx = atomicAdd(&g_ovf_cnt, 1);
        g_ovf_edges[idx] = make_int2(s, d);
    }
}

// ---------------------------------------------------------------------------
// Kernel 2b: gather-aggregate; writes tf32-rounded mean. MLP=4 gather.
// ---------------------------------------------------------------------------
__global__ void aggregate_kernel(int N) {
    int warp = threadIdx.x >> 5;
    int lane = threadIdx.x & 31;
    int d    = blockIdx.x * 8 + warp;
    if (d >= N) return;

    const int n  = g_cnt_i[d];
    const int nb = n < CAP ? n : CAP;
    const int* bk = &g_bucket[(size_t)d * CAP];

    float4 acc = make_float4(0.f, 0.f, 0.f, 0.f);
    int j = 0;
    for (; j + 4 <= nb; j += 4) {
        int s0 = __ldg(&bk[j]);
        int s1 = __ldg(&bk[j + 1]);
        int s2 = __ldg(&bk[j + 2]);
        int s3 = __ldg(&bk[j + 3]);
        float4 v0 = reinterpret_cast<const float4*>(g_h)[(size_t)s0 * 32 + lane];
        float4 v1 = reinterpret_cast<const float4*>(g_h)[(size_t)s1 * 32 + lane];
        float4 v2 = reinterpret_cast<const float4*>(g_h)[(size_t)s2 * 32 + lane];
        float4 v3 = reinterpret_cast<const float4*>(g_h)[(size_t)s3 * 32 + lane];
        acc.x += (v0.x + v1.x) + (v2.x + v3.x);
        acc.y += (v0.y + v1.y) + (v2.y + v3.y);
        acc.z += (v0.z + v1.z) + (v2.z + v3.z);
        acc.w += (v0.w + v1.w) + (v2.w + v3.w);
    }
    for (; j < nb; ++j) {
        int s0 = __ldg(&bk[j]);
        float4 v0 = reinterpret_cast<const float4*>(g_h)[(size_t)s0 * 32 + lane];
        acc.x += v0.x; acc.y += v0.y; acc.z += v0.z; acc.w += v0.w;
    }
    const int novf = g_ovf_cnt;     // 0 in practice
    for (int t = 0; t < novf; ++t) {
        int2 p = g_ovf_edges[t];
        if (p.y == d) {
            float4 v = reinterpret_cast<const float4*>(g_h)[(size_t)p.x * 32 + lane];
            acc.x += v.x; acc.y += v.y; acc.z += v.z; acc.w += v.w;
        }
    }
    const float inv = 1.0f / fmaxf((float)n, 1.0f);
    float4 o;
    o.x = f2tf32f(acc.x * inv);
    o.y = f2tf32f(acc.y * inv);
    o.z = f2tf32f(acc.z * inv);
    o.w = f2tf32f(acc.w * inv);
    reinterpret_cast<float4*>(g_agg)[(size_t)d * 32 + lane] = o;
}

// ---------------------------------------------------------------------------
// Kernel 3: tf32 mma.sync GEMM, cp.async double-buffered K chunks.
//   out = [mean_agg | h] (Nx256) @ Wcat^T + b_l
// Block M=128, N=128; K in 4 chunks of 64. 512 threads = 16 warps
//   (4 mg x 4 ng); warp tile 32x32 = 2 mblk x 4 nblk -> 256 crossbar-B/MMA.
// Reg ceiling at 512 thr = 128 -> acc 32 + frags 16 fit without spills.
// ---------------------------------------------------------------------------
__global__ void __launch_bounds__(512, 1)
gemm_mma_kernel(const float* __restrict__ Wl, const float* __restrict__ bl,
                const float* __restrict__ Wr, float* __restrict__ out, int N) {
    extern __shared__ float sm[];
    float* Wt   = sm;                          // [128][PITCH]
    float* bufs = sm + 128 * PITCH;            // 2 x [128][IPITCH]
    const uint32_t bufs_u32 = smem_u32(bufs);

    const int tid  = threadIdx.x;
    const int lane = tid & 31;
    const int wid  = tid >> 5;
    const int g    = lane >> 2;
    const int t    = lane & 3;
    const int mg   = wid >> 2;        // 0..3: rows mg*32
    const int ng   = wid & 3;         // 0..3: cols ng*32
    const int r0   = mg * 32;
    const int c0   = ng * 32;

    // Stage weights (tf32-rounded): Wt[n][k]
    for (int idx = tid; idx < 128 * 256; idx += 512) {
        int n = idx >> 8;
        int k = idx & 255;
        float w = (k < 128) ? Wl[n * 128 + k] : Wr[n * 128 + (k - 128)];
        Wt[n * PITCH + k] = f2tf32f(w);
    }

    float2 bias[4];
#pragma unroll
    for (int n = 0; n < 4; ++n) {
        int col = c0 + n * 8 + 2 * t;
        bias[n].x = __ldg(&bl[col]);
        bias[n].y = __ldg(&bl[col + 1]);
    }

    const int sr  = tid >> 4;          // staging row 0..31 (u adds +32)
    const int sfo = tid & 15;          // staging float4 col 0..15
    const int ntiles = (N + 127) / 128;

    for (int tile = blockIdx.x; tile < ntiles; tile += gridDim.x) {
        const int rowbase = tile * 128;

        // prefetch chunk 0 (cols 0..63 = g_agg cols 0..63)
#pragma unroll
        for (int u = 0; u < 4; ++u) {
            int r = sr + u * 32;
            int grow = rowbase + r;
            const float* src = g_agg + (size_t)grow * 128 + sfo * 4;
            uint32_t dst = bufs_u32 + (uint32_t)(r * IPITCH + sfo * 4) * 4u;
            cp16(dst, src, grow < N);
        }
        asm volatile("cp.async.commit_group;" ::: "memory");

        float acc[2][4][4];
#pragma unroll
        for (int m = 0; m < 2; ++m)
#pragma unroll
            for (int n = 0; n < 4; ++n)
#pragma unroll
                for (int i = 0; i < 4; ++i) acc[m][n][i] = 0.0f;

#pragma unroll
        for (int c = 0; c < 4; ++c) {
            if (c < 3) {
                const int cc = c + 1;
#pragma unroll
                for (int u = 0; u < 4; ++u) {
                    int r = sr + u * 32;
                    int grow = rowbase + r;
                    int colb = cc * 64 + sfo * 4;   // 64..255
                    const float* src = (colb < 128)
                        ? g_agg + (size_t)grow * 128 + colb
                        : g_h   + (size_t)grow * 128 + (colb - 128);
                    uint32_t dst = bufs_u32
                        + (uint32_t)(((cc & 1) * 128 + r) * IPITCH + sfo * 4) * 4u;
                    cp16(dst, src, grow < N);
                }
                asm volatile("cp.async.commit_group;" ::: "memory");
                asm volatile("cp.async.wait_group 1;" ::: "memory");
            } else {
                asm volatile("cp.async.wait_group 0;" ::: "memory");
            }
            __syncthreads();

            const float* Abase = bufs + (c & 1) * 128 * IPITCH + (r0 + g) * IPITCH + t;
            const float* Bbase = Wt + (c0 + g) * PITCH + c * 64 + t;

#pragma unroll
            for (int ks = 0; ks < 8; ++ks) {
                const float* ap = Abase + ks * 8;
                const float* bp = Bbase + ks * 8;

                uint32_t a[2][4];
#pragma unroll
                for (int m = 0; m < 2; ++m) {
                    const float* p = ap + m * 16 * IPITCH;
                    a[m][0] = __float_as_uint(p[0]);
                    a[m][1] = __float_as_uint(p[8 * IPITCH]);
                    a[m][2] = __float_as_uint(p[4]);
                    a[m][3] = __float_as_uint(p[8 * IPITCH + 4]);
                }
                uint32_t b[4][2];
#pragma unroll
                for (int n = 0; n < 4; ++n) {
                    const float* p = bp + n * 8 * PITCH;
                    b[n][0] = __float_as_uint(p[0]);
                    b[n][1] = __float_as_uint(p[4]);
                }
#pragma unroll
                for (int m = 0; m < 2; ++m)
#pragma unroll
                    for (int n = 0; n < 4; ++n) {
                        asm("mma.sync.aligned.m16n8k8.row.col.f32.tf32.tf32.f32 "
                            "{%0,%1,%2,%3}, {%4,%5,%6,%7}, {%8,%9}, {%0,%1,%2,%3};"
                            : "+f"(acc[m][n][0]), "+f"(acc[m][n][1]),
                              "+f"(acc[m][n][2]), "+f"(acc[m][n][3])
                            : "r"(a[m][0]), "r"(a[m][1]), "r"(a[m][2]), "r"(a[m][3]),
                              "r"(b[n][0]), "r"(b[n][1]));
                    }
            }
            __syncthreads();
        }

        // Epilogue: rows {r0 + m*16 + g, +8}, cols c0 + n*8 + 2t (+1)
#pragma unroll
        for (int m = 0; m < 2; ++m) {
            int row0 = rowbase + r0 + m * 16 + g;
            int row1 = row0 + 8;
#pragma unroll
            for (int n = 0; n < 4; ++n) {
                int colh = (c0 + n * 8 + 2 * t) >> 1;
                if (row0 < N) {
                    float2 o0 = make_float2(acc[m][n][0] + bias[n].x,
                                            acc[m][n][1] + bias[n].y);
                    reinterpret_cast<float2*>(out)[(size_t)row0 * 64 + colh] = o0;
                }
                if (row1 < N) {
                    float2 o1 = make_float2(acc[m][n][2] + bias[n].x,
                                            acc[m][n][3] + bias[n].y);
                    reinterpret_cast<float2*>(out)[(size_t)row1 * 64 + colh] = o1;
                }
            }
        }
    }
}

// ---------------------------------------------------------------------------
extern "C" void kernel_launch(void* const* d_in, const int* in_sizes, int n_in,
                              void* d_out, int out_size) {
    const float* x     = (const float*)d_in[0];
    const int*   eidx  = (const int*)d_in[1];   // int32 (JAX x64 disabled)
    const float* mask  = (const float*)d_in[2];
    const float* gamma = (const float*)d_in[3];
    const float* beta  = (const float*)d_in[4];
    const float* Wl    = (const float*)d_in[5];
    const float* bl    = (const float*)d_in[6];
    const float* Wr    = (const float*)d_in[7];
    float*       out   = (float*)d_out;

    const int N = in_sizes[0] / D;
    const int E = in_sizes[1] / 2;

    ln_relu_drop_kernel<<<(N + 7) / 8, 256>>>(x, mask, gamma, beta, N);
    fill_kernel<<<(E + 255) / 256, 256>>>(eidx, E);
    aggregate_kernel<<<(N + 7) / 8, 256>>>(N);

    {
        int smem = (128 * PITCH + 2 * 128 * IPITCH) * (int)sizeof(float);  // 202,752 B
        cudaFuncSetAttribute(gemm_mma_kernel, cudaFuncAttributeMaxDynamicSharedMemorySize, smem);
        int nsm = 148;
        cudaDeviceGetAttribute(&nsm, cudaDevAttrMultiProcessorCount, 0);
        gemm_mma_kernel<<<nsm, 512, smem>>>(Wl, bl, Wr, out, N);
    }
}

// round 15
// speedup vs baseline: 1.8206x; 1.0572x over previous
#include <cuda_runtime.h>
#include <cstdint>

#define D 128
#define NMAX 100000
#define EMAX 600000
#define CAP 64
#define PITCH  260   // weights pitch: %32==4 -> conflict-free fragment rows
#define IPITCH 36    // ins chunk pitch (32 cols + pad): %32==4, 16B-aligned rows

// Scratch
__device__ __align__(16) float g_h[(size_t)NMAX * D];
__device__ __align__(16) float g_agg[(size_t)NMAX * D];   // mean_agg (tf32 vals)
__device__ int  g_cnt_i[NMAX];
__device__ int  g_bucket[(size_t)NMAX * CAP];
__device__ int2 g_ovf_edges[EMAX];
__device__ int  g_ovf_cnt;

__device__ __forceinline__ float f2tf32f(float f) {
    uint32_t t;
    asm("cvt.rna.tf32.f32 %0, %1;" : "=r"(t) : "f"(f));
    return __uint_as_float(t);
}
__device__ __forceinline__ uint32_t smem_u32(const void* p) {
    uint32_t a;
    asm("{ .reg .u64 t; cvta.to.shared.u64 t, %1; cvt.u32.u64 %0, t; }" : "=r"(a) : "l"(p));
    return a;
}
__device__ __forceinline__ void cp16(uint32_t dst, const void* src, bool pred) {
    int sz = pred ? 16 : 0;   // src-size 0 -> zero-fill
    asm volatile("cp.async.cg.shared.global [%0], [%1], 16, %2;"
                 :: "r"(dst), "l"(src), "r"(sz) : "memory");
}

// ---------------------------------------------------------------------------
// Kernel 1: LayerNorm -> ReLU -> dropout; h pre-rounded to tf32 (RNA).
// Zeroes g_cnt_i and g_ovf_cnt for the fill that follows.
// ---------------------------------------------------------------------------
__global__ void ln_relu_drop_kernel(const float* __restrict__ x,
                                    const float* __restrict__ mask,
                                    const float* __restrict__ gamma,
                                    const float* __restrict__ beta,
                                    int N) {
    int warp = threadIdx.x >> 5;
    int lane = threadIdx.x & 31;
    int row  = blockIdx.x * 8 + warp;
    if (blockIdx.x == 0 && threadIdx.x == 0) g_ovf_cnt = 0;
    if (row >= N) return;

    const float4 xv = reinterpret_cast<const float4*>(x)[row * 32 + lane];
    float s  = xv.x + xv.y + xv.z + xv.w;
    float ss = xv.x * xv.x + xv.y * xv.y + xv.z * xv.z + xv.w * xv.w;
#pragma unroll
    for (int o = 16; o > 0; o >>= 1) {
        s  += __shfl_xor_sync(0xFFFFFFFFu, s,  o);
        ss += __shfl_xor_sync(0xFFFFFFFFu, ss, o);
    }
    const float mu   = s * (1.0f / 128.0f);
    const float var  = ss * (1.0f / 128.0f) - mu * mu;
    const float rstd = rsqrtf(var + 1e-5f);

    const float4 g = reinterpret_cast<const float4*>(gamma)[lane];
    const float4 b = reinterpret_cast<const float4*>(beta)[lane];
    const float4 m = reinterpret_cast<const float4*>(mask)[row * 32 + lane];

    float4 hv;
    hv.x = f2tf32f(fmaxf((xv.x - mu) * rstd * g.x + b.x, 0.0f) * m.x);
    hv.y = f2tf32f(fmaxf((xv.y - mu) * rstd * g.y + b.y, 0.0f) * m.y);
    hv.z = f2tf32f(fmaxf((xv.z - mu) * rstd * g.z + b.z, 0.0f) * m.z);
    hv.w = f2tf32f(fmaxf((xv.w - mu) * rstd * g.w + b.w, 0.0f) * m.w);

    reinterpret_cast<float4*>(g_h)[row * 32 + lane] = hv;
    if (lane == 0) g_cnt_i[row] = 0;
}

// ---------------------------------------------------------------------------
// Kernel 2a: bucket fill (int atomics only).
// ---------------------------------------------------------------------------
__global__ void fill_kernel(const int* __restrict__ ei, int E) {
    int e = blockIdx.x * blockDim.x + threadIdx.x;
    if (e >= E) return;
    const int s = __ldg(&ei[e]);
    const int d = __ldg(&ei[E + e]);
    int pos = atomicAdd(&g_cnt_i[d], 1);
    if (pos < CAP) g_bucket[(size_t)d * CAP + pos] = s;
    else {
        int idx = atomicAdd(&g_ovf_cnt, 1);
        g_ovf_edges[idx] = make_int2(s, d);
    }
}

// ---------------------------------------------------------------------------
// Kernel 2b: gather-aggregate; writes tf32-rounded mean. MLP=4 gather.
// ---------------------------------------------------------------------------
__global__ void aggregate_kernel(int N) {
    int warp = threadIdx.x >> 5;
    int lane = threadIdx.x & 31;
    int d    = blockIdx.x * 8 + warp;
    if (d >= N) return;

    const int n  = g_cnt_i[d];
    const int nb = n < CAP ? n : CAP;
    const int* bk = &g_bucket[(size_t)d * CAP];

    float4 acc = make_float4(0.f, 0.f, 0.f, 0.f);
    int j = 0;
    for (; j + 4 <= nb; j += 4) {
        int s0 = __ldg(&bk[j]);
        int s1 = __ldg(&bk[j + 1]);
        int s2 = __ldg(&bk[j + 2]);
        int s3 = __ldg(&bk[j + 3]);
        float4 v0 = reinterpret_cast<const float4*>(g_h)[(size_t)s0 * 32 + lane];
        float4 v1 = reinterpret_cast<const float4*>(g_h)[(size_t)s1 * 32 + lane];
        float4 v2 = reinterpret_cast<const float4*>(g_h)[(size_t)s2 * 32 + lane];
        float4 v3 = reinterpret_cast<const float4*>(g_h)[(size_t)s3 * 32 + lane];
        acc.x += (v0.x + v1.x) + (v2.x + v3.x);
        acc.y += (v0.y + v1.y) + (v2.y + v3.y);
        acc.z += (v0.z + v1.z) + (v2.z + v3.z);
        acc.w += (v0.w + v1.w) + (v2.w + v3.w);
    }
    for (; j < nb; ++j) {
        int s0 = __ldg(&bk[j]);
        float4 v0 = reinterpret_cast<const float4*>(g_h)[(size_t)s0 * 32 + lane];
        acc.x += v0.x; acc.y += v0.y; acc.z += v0.z; acc.w += v0.w;
    }
    const int novf = g_ovf_cnt;     // 0 in practice
    for (int t = 0; t < novf; ++t) {
        int2 p = g_ovf_edges[t];
        if (p.y == d) {
            float4 v = reinterpret_cast<const float4*>(g_h)[(size_t)p.x * 32 + lane];
            acc.x += v.x; acc.y += v.y; acc.z += v.z; acc.w += v.w;
        }
    }
    const float inv = 1.0f / fmaxf((float)n, 1.0f);
    float4 o;
    o.x = f2tf32f(acc.x * inv);
    o.y = f2tf32f(acc.y * inv);
    o.z = f2tf32f(acc.z * inv);
    o.w = f2tf32f(acc.w * inv);
    reinterpret_cast<float4*>(g_agg)[(size_t)d * 32 + lane] = o;
}

// ---------------------------------------------------------------------------
// Kernel 3: tf32 mma.sync GEMM, cp.async double-buffered K chunks.
//   out = [mean_agg | h] (Nx256) @ Wcat^T + b_l
// Block tile M=256, N=128; K in 8 chunks of 32. 512 threads = 16 warps
//   (4 mg x 4 ng); warp tile 64x32 = 4 mblk x 4 nblk:
//   24 LDS feed 16 MMAs per ks (1.5 instr/MMA, 192 crossbar-B/MMA).
// Regs: acc 64 + frags 24 + addr ~25 = ~115 < 128 ceiling at 512 thr.
// smem: Wt[128][PITCH] 133.1KB + 2 x [256][IPITCH] 73.7KB = 206.8KB.
// ---------------------------------------------------------------------------
__global__ void __launch_bounds__(512, 1)
gemm_mma_kernel(const float* __restrict__ Wl, const float* __restrict__ bl,
                const float* __restrict__ Wr, float* __restrict__ out, int N) {
    extern __shared__ float sm[];
    float* Wt   = sm;                          // [128][PITCH]
    float* bufs = sm + 128 * PITCH;            // 2 x [256][IPITCH]
    const uint32_t bufs_u32 = smem_u32(bufs);

    const int tid  = threadIdx.x;
    const int lane = tid & 31;
    const int wid  = tid >> 5;
    const int g    = lane >> 2;
    const int t    = lane & 3;
    const int mg   = wid >> 2;        // 0..3: rows mg*64
    const int ng   = wid & 3;         // 0..3: cols ng*32
    const int r0   = mg * 64;
    const int c0   = ng * 32;

    // Stage weights (tf32-rounded): Wt[n][k]
    for (int idx = tid; idx < 128 * 256; idx += 512) {
        int n = idx >> 8;
        int k = idx & 255;
        float w = (k < 128) ? Wl[n * 128 + k] : Wr[n * 128 + (k - 128)];
        Wt[n * PITCH + k] = f2tf32f(w);
    }

    float2 bias[4];
#pragma unroll
    for (int n = 0; n < 4; ++n) {
        int col = c0 + n * 8 + 2 * t;
        bias[n].x = __ldg(&bl[col]);
        bias[n].y = __ldg(&bl[col + 1]);
    }

    const int sr  = tid >> 3;          // staging row 0..63 (u adds +64)
    const int sfo = tid & 7;           // staging float4 col 0..7
    const int ntiles = (N + 255) / 256;

    for (int tile = blockIdx.x; tile < ntiles; tile += gridDim.x) {
        const int rowbase = tile * 256;

        // prefetch chunk 0 (cols 0..31 = g_agg cols 0..31)
#pragma unroll
        for (int u = 0; u < 4; ++u) {
            int r = sr + u * 64;
            int grow = rowbase + r;
            const float* src = g_agg + (size_t)grow * 128 + sfo * 4;
            uint32_t dst = bufs_u32 + (uint32_t)(r * IPITCH + sfo * 4) * 4u;
            cp16(dst, src, grow < N);
        }
        asm volatile("cp.async.commit_group;" ::: "memory");

        float acc[4][4][4];
#pragma unroll
        for (int m = 0; m < 4; ++m)
#pragma unroll
            for (int n = 0; n < 4; ++n)
#pragma unroll
                for (int i = 0; i < 4; ++i) acc[m][n][i] = 0.0f;

#pragma unroll
        for (int c = 0; c < 8; ++c) {
            if (c < 7) {
                const int cc = c + 1;
#pragma unroll
                for (int u = 0; u < 4; ++u) {
                    int r = sr + u * 64;
                    int grow = rowbase + r;
                    int colb = cc * 32 + sfo * 4;   // 32..255
                    const float* src = (colb < 128)
                        ? g_agg + (size_t)grow * 128 + colb
                        : g_h   + (size_t)grow * 128 + (colb - 128);
                    uint32_t dst = bufs_u32
                        + (uint32_t)(((cc & 1) * 256 + r) * IPITCH + sfo * 4) * 4u;
                    cp16(dst, src, grow < N);
                }
                asm volatile("cp.async.commit_group;" ::: "memory");
                asm volatile("cp.async.wait_group 1;" ::: "memory");
            } else {
                asm volatile("cp.async.wait_group 0;" ::: "memory");
            }
            __syncthreads();

            const float* Abase = bufs + (c & 1) * 256 * IPITCH + (r0 + g) * IPITCH + t;
            const float* Bbase = Wt + (c0 + g) * PITCH + c * 32 + t;

#pragma unroll
            for (int ks = 0; ks < 4; ++ks) {
                const float* ap = Abase + ks * 8;
                const float* bp = Bbase + ks * 8;

                uint32_t a[4][4];
#pragma unroll
                for (int m = 0; m < 4; ++m) {
                    const float* p = ap + m * 16 * IPITCH;
                    a[m][0] = __float_as_uint(p[0]);
                    a[m][1] = __float_as_uint(p[8 * IPITCH]);
                    a[m][2] = __float_as_uint(p[4]);
                    a[m][3] = __float_as_uint(p[8 * IPITCH + 4]);
                }
                uint32_t b[4][2];
#pragma unroll
                for (int n = 0; n < 4; ++n) {
                    const float* p = bp + n * 8 * PITCH;
                    b[n][0] = __float_as_uint(p[0]);
                    b[n][1] = __float_as_uint(p[4]);
                }
#pragma unroll
                for (int m = 0; m < 4; ++m)
#pragma unroll
                    for (int n = 0; n < 4; ++n) {
                        asm("mma.sync.aligned.m16n8k8.row.col.f32.tf32.tf32.f32 "
                            "{%0,%1,%2,%3}, {%4,%5,%6,%7}, {%8,%9}, {%0,%1,%2,%3};"
                            : "+f"(acc[m][n][0]), "+f"(acc[m][n][1]),
                              "+f"(acc[m][n][2]), "+f"(acc[m][n][3])
                            : "r"(a[m][0]), "r"(a[m][1]), "r"(a[m][2]), "r"(a[m][3]),
                              "r"(b[n][0]), "r"(b[n][1]));
                    }
            }
            __syncthreads();
        }

        // Epilogue: rows {r0 + m*16 + g, +8}, cols c0 + n*8 + 2t (+1)
#pragma unroll
        for (int m = 0; m < 4; ++m) {
            int row0 = rowbase + r0 + m * 16 + g;
            int row1 = row0 + 8;
#pragma unroll
            for (int n = 0; n < 4; ++n) {
                int colh = (c0 + n * 8 + 2 * t) >> 1;
                if (row0 < N) {
                    float2 o0 = make_float2(acc[m][n][0] + bias[n].x,
                                            acc[m][n][1] + bias[n].y);
                    reinterpret_cast<float2*>(out)[(size_t)row0 * 64 + colh] = o0;
                }
                if (row1 < N) {
                    float2 o1 = make_float2(acc[m][n][2] + bias[n].x,
                                            acc[m][n][3] + bias[n].y);
                    reinterpret_cast<float2*>(out)[(size_t)row1 * 64 + colh] = o1;
                }
            }
        }
    }
}

// ---------------------------------------------------------------------------
extern "C" void kernel_launch(void* const* d_in, const int* in_sizes, int n_in,
                              void* d_out, int out_size) {
    const float* x     = (const float*)d_in[0];
    const int*   eidx  = (const int*)d_in[1];   // int32 (JAX x64 disabled)
    const float* mask  = (const float*)d_in[2];
    const float* gamma = (const float*)d_in[3];
    const float* beta  = (const float*)d_in[4];
    const float* Wl    = (const float*)d_in[5];
    const float* bl    = (const float*)d_in[6];
    const float* Wr    = (const float*)d_in[7];
    float*       out   = (float*)d_out;

    const int N = in_sizes[0] / D;
    const int E = in_sizes[1] / 2;

    ln_relu_drop_kernel<<<(N + 7) / 8, 256>>>(x, mask, gamma, beta, N);
    fill_kernel<<<(E + 255) / 256, 256>>>(eidx, E);
    aggregate_kernel<<<(N + 7) / 8, 256>>>(N);

    {
        int smem = (128 * PITCH + 2 * 256 * IPITCH) * (int)sizeof(float);  // 206,848 B
        cudaFuncSetAttribute(gemm_mma_kernel, cudaFuncAttributeMaxDynamicSharedMemorySize, smem);
        int nsm = 148;
        cudaDeviceGetAttribute(&nsm, cudaDevAttrMultiProcessorCount, 0);
        gemm_mma_kernel<<<nsm, 512, smem>>>(Wl, bl, Wr, out, N);
    }
}